// round 16
// baseline (speedup 1.0000x reference)
#include <cuda_runtime.h>
#include <cuda_bf16.h>
#include <cstdint>
#include <math.h>

#define T_TOTAL 1024
#define BATCH   32
#define D_IN    512
#define NC0     1024
#define NC1     1024
#define NC2     512
#define ROWS    (T_TOTAL * BATCH)   // 32768
#define CHUNKS  128
#define HLT     8

// ---------------------------------------------------------------------------
// Scratch (device globals; no cudaMalloc allowed)
// ---------------------------------------------------------------------------
__device__ float g_H0[(size_t)ROWS * NC0];
__device__ float g_H1[(size_t)ROWS * NC1];
__device__ float g_H2[(size_t)ROWS * NC2];
__device__ float g_mean[CHUNKS * NC0];
__device__ float g_var [CHUNKS * NC0];

__device__ __nv_bfloat16 g_S0[(size_t)ROWS * NC0];   // spikes (exact in bf16)
__device__ __nv_bfloat16 g_S1[(size_t)ROWS * NC1];
__device__ __nv_bfloat16 g_W1h[NC1 * NC0], g_W1m[NC1 * NC0], g_W1l[NC1 * NC0];
__device__ __nv_bfloat16 g_W2h[NC2 * NC1], g_W2m[NC2 * NC1], g_W2l[NC2 * NC1];

// ---------------------------------------------------------------------------
// PTX helpers (family-agnostic: mma.sync / ldmatrix / cp.async only)
// ---------------------------------------------------------------------------
__device__ __forceinline__ uint32_t smem_to_u32(const void* p) {
    uint32_t a;
    asm("{ .reg .u64 t; cvta.to.shared.u64 t, %1; cvt.u32.u64 %0, t; }" : "=r"(a) : "l"(p));
    return a;
}
__device__ __forceinline__ void ldsm_x4(uint32_t* r, uint32_t addr) {
    asm volatile("ldmatrix.sync.aligned.m8n8.x4.shared.b16 {%0,%1,%2,%3}, [%4];"
        : "=r"(r[0]), "=r"(r[1]), "=r"(r[2]), "=r"(r[3]) : "r"(addr));
}
__device__ __forceinline__ void mma16816(float* c, const uint32_t* a, const uint32_t* b) {
    asm volatile("mma.sync.aligned.m16n8k16.row.col.f32.bf16.bf16.f32 "
        "{%0,%1,%2,%3}, {%4,%5,%6,%7}, {%8,%9}, {%0,%1,%2,%3};"
        : "+f"(c[0]), "+f"(c[1]), "+f"(c[2]), "+f"(c[3])
        : "r"(a[0]), "r"(a[1]), "r"(a[2]), "r"(a[3]), "r"(b[0]), "r"(b[1]));
}
__device__ __forceinline__ void cpasync16(uint32_t dst, const void* src) {
    asm volatile("cp.async.cg.shared.global [%0], [%1], 16;" :: "r"(dst), "l"(src));
}

// SW64 swizzle (layout-only; bit-identical data)
#define SWZ64(off) ((off) ^ (((off) >> 3) & 0x30))
#define TB64   (128 * 64)          // one 128x32 bf16 tile = 8192 B
#define STG64  (4 * TB64)          // 1 A tile + 3 B tiles  = 32768 B
#define SMEM_TC (3 * STG64)        // 3 stages = 98304 B -> 2 CTAs/SM

// load one 128x32 bf16 tile: 512 granules of 16B, 2 per thread
__device__ __forceinline__ void load_tile(uint32_t dst, const __nv_bfloat16* __restrict__ src,
                                          int row0, int ldk, int k0, int tid)
{
    const char* gb = (const char*)(src + (size_t)row0 * ldk + k0);
    const size_t rs = (size_t)ldk * 2;
#pragma unroll
    for (int i = 0; i < 2; i++) {
        int idx = i * 256 + tid;
        int r = idx >> 2, g = idx & 3;
        uint32_t off = (uint32_t)(r * 64 + g * 16);
        cpasync16(dst + SWZ64(off), gb + (size_t)r * rs + g * 16);
    }
}

// ---------------------------------------------------------------------------
// HMMA GEMM for spike layers: C[M,N] = A * (Wh+Wm+Wl)^T + bias
// A = bf16 spikes (exact). 128x128 block tile, BK=32, 3-stage cp.async,
// 8 warps in 2(M)x4(N) (warp tile 64x32). SW64 swizzle; 2 CTAs/SM.
// Per-element accumulation sequence identical to the R4-proven order.
// ---------------------------------------------------------------------------
template <int N, int K>
__global__ void __launch_bounds__(256, 2) gemm_spike(
    const __nv_bfloat16* __restrict__ A,
    const __nv_bfloat16* __restrict__ Wh,
    const __nv_bfloat16* __restrict__ Wm,
    const __nv_bfloat16* __restrict__ Wl,
    const float* __restrict__ bias,
    float* __restrict__ C)
{
    constexpr int NCH = K / 32;
    const __nv_bfloat16* Bp[3] = {Wh, Wm, Wl};

    extern __shared__ __align__(128) char smem[];
    const uint32_t sb = smem_to_u32(smem);
    const int tid = threadIdx.x;
    const int l   = tid & 31;
    const int wid = tid >> 5;
    const int wm  = wid & 1;       // 2 warps along M (64 rows each)
    const int wn  = wid >> 1;      // 4 warps along N (32 cols each)
    const int n0  = blockIdx.x * 128;
    const int m0  = blockIdx.y * 128;

    float acc[4][4][4];
#pragma unroll
    for (int i = 0; i < 4; i++)
#pragma unroll
        for (int j = 0; j < 4; j++)
#pragma unroll
            for (int q = 0; q < 4; q++) acc[i][j][q] = 0.0f;

    const int rA = l & 15;
    const int cA = l >> 4;
    const int rB = ((l >> 4) & 1) * 8 + (l & 7);
    const int cB = (l >> 3) & 1;

#pragma unroll
    for (int pc = 0; pc < 2; pc++) {
        const uint32_t so = sb + (uint32_t)pc * STG64;
        load_tile(so, A, m0, K, pc * 32, tid);
#pragma unroll
        for (int b = 0; b < 3; b++) load_tile(so + (1 + b) * TB64, Bp[b], n0, K, pc * 32, tid);
        asm volatile("cp.async.commit_group;" ::: "memory");
    }

    for (int ch = 0; ch < NCH; ch++) {
        if (ch == NCH - 1) asm volatile("cp.async.wait_group 0;" ::: "memory");
        else               asm volatile("cp.async.wait_group 1;" ::: "memory");
        __syncthreads();

        if (ch + 2 < NCH) {
            const uint32_t so = sb + (uint32_t)((ch + 2) % 3) * STG64;
            const int k0 = (ch + 2) * 32;
            load_tile(so, A, m0, K, k0, tid);
#pragma unroll
            for (int b = 0; b < 3; b++) load_tile(so + (1 + b) * TB64, Bp[b], n0, K, k0, tid);
            asm volatile("cp.async.commit_group;" ::: "memory");
        }

        const uint32_t so = sb + (uint32_t)(ch % 3) * STG64;
#pragma unroll
        for (int ks = 0; ks < 2; ks++) {
            uint32_t af[4][4];
#pragma unroll
            for (int tm = 0; tm < 4; tm++) {
                uint32_t off = (uint32_t)((wm * 64 + tm * 16 + rA) * 64 + (ks * 2 + cA) * 16);
                ldsm_x4(af[tm], so + SWZ64(off));
            }
#pragma unroll
            for (int b = 0; b < 3; b++) {
                uint32_t bf[2][4];
#pragma unroll
                for (int g = 0; g < 2; g++) {
                    uint32_t off = (uint32_t)((wn * 32 + g * 16 + rB) * 64 + (ks * 2 + cB) * 16);
                    ldsm_x4(bf[g], so + (1 + b) * TB64 + SWZ64(off));
                }
#pragma unroll
                for (int tm = 0; tm < 4; tm++)
#pragma unroll
                    for (int n8 = 0; n8 < 4; n8++)
                        mma16816(acc[tm][n8], af[tm], &bf[n8 >> 1][(n8 & 1) * 2]);
            }
        }
    }

    // epilogue: acc + bias -> C (row-major fp32)
#pragma unroll
    for (int tm = 0; tm < 4; tm++) {
        const int mr = m0 + wm * 64 + tm * 16 + (l >> 2);
#pragma unroll
        for (int n8 = 0; n8 < 4; n8++) {
            const int col = n0 + wn * 32 + n8 * 8 + (l & 3) * 2;
            const float bx = bias[col], by = bias[col + 1];
            float2 v0, v1;
            v0.x = acc[tm][n8][0] + bx; v0.y = acc[tm][n8][1] + by;
            v1.x = acc[tm][n8][2] + bx; v1.y = acc[tm][n8][3] + by;
            *(float2*)(C + (size_t)mr * N + col)       = v0;
            *(float2*)(C + (size_t)(mr + 8) * N + col) = v1;
        }
    }
}

// ---------------------------------------------------------------------------
// fp32 GEMM for layer 0 — pipelined (double-buffered SMEM + register
// prefetch, one sync per k-chunk); R1-proven FMA order, bit-identical.
// ---------------------------------------------------------------------------
__device__ __forceinline__ int bswz(int col) {
    int g = col >> 2;
    int gs = g ^ (g >> 3);
    return (gs << 2) | (col & 3);
}

template <int N, int K>
__global__ __launch_bounds__(256, 2)
void gemm_f32(const float* __restrict__ A, const float* __restrict__ B,
              const float* __restrict__ bias, float* __restrict__ C)
{
    __shared__ float As[2][16][128];
    __shared__ float Bs[2][16][128];

    const int tid = threadIdx.x;
    const int m0  = blockIdx.y * 128;
    const int n0  = blockIdx.x * 128;
    const int tm  = (tid >> 4) << 3;
    const int tn  = (tid & 15) << 3;
    const int lr  = tid >> 2;
    const int lc  = (tid & 3) << 2;

    float acc[8][8];
#pragma unroll
    for (int i = 0; i < 8; i++)
#pragma unroll
        for (int j = 0; j < 8; j++) acc[i][j] = 0.0f;

    float4 av[2], bv[2];
#pragma unroll
    for (int h = 0; h < 2; h++) {
        const int r = lr + h * 64;
        av[h] = *(const float4*)(A + (size_t)(m0 + r) * K + lc);
        bv[h] = *(const float4*)(B + (size_t)(n0 + r) * K + lc);
    }

    for (int k0 = 0; k0 < K; k0 += 16) {
        const int buf = (k0 >> 4) & 1;
#pragma unroll
        for (int h = 0; h < 2; h++) {
            const int r = lr + h * 64;
            As[buf][lc + 0][r] = av[h].x; As[buf][lc + 1][r] = av[h].y;
            As[buf][lc + 2][r] = av[h].z; As[buf][lc + 3][r] = av[h].w;
            const int rsw = bswz(r);
            Bs[buf][lc + 0][rsw] = bv[h].x; Bs[buf][lc + 1][rsw] = bv[h].y;
            Bs[buf][lc + 2][rsw] = bv[h].z; Bs[buf][lc + 3][rsw] = bv[h].w;
        }
        if (k0 + 16 < K) {
#pragma unroll
            for (int h = 0; h < 2; h++) {
                const int r = lr + h * 64;
                av[h] = *(const float4*)(A + (size_t)(m0 + r) * K + (k0 + 16 + lc));
                bv[h] = *(const float4*)(B + (size_t)(n0 + r) * K + (k0 + 16 + lc));
            }
        }
        __syncthreads();
#pragma unroll
        for (int kk = 0; kk < 16; kk++) {
            float4 a0 = *(const float4*)&As[buf][kk][tm];
            float4 a1 = *(const float4*)&As[buf][kk][tm + 4];
            float4 b0 = *(const float4*)&Bs[buf][kk][bswz(tn)];
            float4 b1 = *(const float4*)&Bs[buf][kk][bswz(tn + 4)];
            float ar[8] = {a0.x, a0.y, a0.z, a0.w, a1.x, a1.y, a1.z, a1.w};
            float br[8] = {b0.x, b0.y, b0.z, b0.w, b1.x, b1.y, b1.z, b1.w};
#pragma unroll
            for (int i = 0; i < 8; i++)
#pragma unroll
                for (int j = 0; j < 8; j++)
                    acc[i][j] = fmaf(ar[i], br[j], acc[i][j]);
        }
    }

#pragma unroll
    for (int i = 0; i < 8; i++) {
        float4 o0, o1;
        o0.x = acc[i][0] + bias[n0 + tn + 0];
        o0.y = acc[i][1] + bias[n0 + tn + 1];
        o0.z = acc[i][2] + bias[n0 + tn + 2];
        o0.w = acc[i][3] + bias[n0 + tn + 3];
        o1.x = acc[i][4] + bias[n0 + tn + 4];
        o1.y = acc[i][5] + bias[n0 + tn + 5];
        o1.z = acc[i][6] + bias[n0 + tn + 6];
        o1.w = acc[i][7] + bias[n0 + tn + 7];
        float* cp = C + (size_t)(m0 + tm + i) * N + n0 + tn;
        *(float4*)cp       = o0;
        *(float4*)(cp + 4) = o1;
    }
}

// ---------------------------------------------------------------------------
// fp32 -> 3-way bf16 split (hi + mid + lo)
// ---------------------------------------------------------------------------
__global__ void __launch_bounds__(256) split3(const float* __restrict__ src,
                                              __nv_bfloat16* __restrict__ h,
                                              __nv_bfloat16* __restrict__ m,
                                              __nv_bfloat16* __restrict__ l, int n)
{
    int i = blockIdx.x * 256 + threadIdx.x;
    if (i >= n) return;
    float x  = src[i];
    __nv_bfloat16 hh = __float2bfloat16(x);
    float r1 = x - __bfloat162float(hh);
    __nv_bfloat16 mm = __float2bfloat16(r1);
    float r2 = r1 - __bfloat162float(mm);
    h[i] = hh; m[i] = mm; l[i] = __float2bfloat16(r2);
}

// ---------------------------------------------------------------------------
// BN stats (two-pass, scalar, 1 channel/thread — R4/R8-proven numerics)
// ---------------------------------------------------------------------------
template <int LAYER, int N>
__global__ __launch_bounds__(256)
void bn_stats()
{
    const float* __restrict__ H =
        (LAYER == 0) ? static_cast<const float*>(g_H0)
        : (LAYER == 1) ? static_cast<const float*>(g_H1)
                       : static_cast<const float*>(g_H2);
    const int ch = blockIdx.x * 256 + threadIdx.x;
    const int c  = blockIdx.y;
    const float* base = H + (size_t)c * 256 * N + ch;

    float s = 0.0f;
#pragma unroll 8
    for (int r = 0; r < 256; r++) s += base[(size_t)r * N];
    const float mu = s * 0.00390625f;

    float vs = 0.0f;
#pragma unroll 8
    for (int r = 0; r < 256; r++) {
        float d = base[(size_t)r * N] - mu;
        vs = fmaf(d, d, vs);
    }
    g_mean[c * N + ch] = mu;
    g_var [c * N + ch] = vs * 0.00390625f;
}

// ---------------------------------------------------------------------------
// Hidden LIF with chunk-ahead prefetch (identical FP sequence per neuron)
// ---------------------------------------------------------------------------
template <int LAYER, int N>
__global__ __launch_bounds__(256)
void lif_hidden(const float* __restrict__ g, const float* __restrict__ bt)
{
    const float* __restrict__ H =
        (LAYER == 0) ? static_cast<const float*>(g_H0)
                     : static_cast<const float*>(g_H1);
    __nv_bfloat16* __restrict__ S =
        (LAYER == 0) ? static_cast<__nv_bfloat16*>(g_S0)
                     : static_cast<__nv_bfloat16*>(g_S1);

    const int idx = blockIdx.x * 256 + threadIdx.x;
    const int n   = idx & (N - 1);
    const float gn  = g[n];
    const float btn = bt[n];
    const size_t trow = (size_t)BATCH * N;
    const __nv_bfloat16 one  = __float2bfloat16(1.0f);
    const __nv_bfloat16 zero = __float2bfloat16(0.0f);

    float hv[2][HLT];
    float mub[2], vrb[2];
#pragma unroll
    for (int t = 0; t < HLT; t++) hv[0][t] = H[(size_t)t * trow + idx];
    mub[0] = g_mean[n];
    vrb[0] = g_var[n];

    float v = 0.0f;
    for (int c = 0; c < CHUNKS; c++) {
        const int cur = c & 1;
        if (c + 1 < CHUNKS) {
            const size_t nb = (size_t)(c + 1) * HLT * trow + idx;
#pragma unroll
            for (int t = 0; t < HLT; t++) hv[cur ^ 1][t] = H[nb + (size_t)t * trow];
            mub[cur ^ 1] = g_mean[(c + 1) * N + n];
            vrb[cur ^ 1] = g_var [(c + 1) * N + n];
        }
        const float mu  = mub[cur];
        const float inv = 1.0f / sqrtf(vrb[cur] + 1e-5f);
        const size_t base = (size_t)c * HLT * trow + idx;
#pragma unroll
        for (int t = 0; t < HLT; t++) {
            const float hb = gn * (hv[cur][t] - mu) * inv + btn;
            v = v + (hb - v) * 0.5f;
            const bool sp = (v >= 1.0f);
            S[base + (size_t)t * trow] = sp ? one : zero;
            if (sp) v = 0.0f;
        }
    }
}

// ---------------------------------------------------------------------------
// Output layer: leaky integrator + chunk mean -> d_out [128, 32, 512]
// ---------------------------------------------------------------------------
__global__ __launch_bounds__(256)
void lif_out(const float* __restrict__ g, const float* __restrict__ bt,
             float* __restrict__ out)
{
    const int idx = blockIdx.x * 256 + threadIdx.x;
    const int n   = idx & (NC2 - 1);
    const float gn  = g[n];
    const float btn = bt[n];
    const size_t trow = (size_t)BATCH * NC2;

    float hv[2][HLT];
    float mub[2], vrb[2];
#pragma unroll
    for (int t = 0; t < HLT; t++) hv[0][t] = g_H2[(size_t)t * trow + idx];
    mub[0] = g_mean[n];
    vrb[0] = g_var[n];

    float v = 0.0f;
    for (int c = 0; c < CHUNKS; c++) {
        const int cur = c & 1;
        if (c + 1 < CHUNKS) {
            const size_t nb = (size_t)(c + 1) * HLT * trow + idx;
#pragma unroll
            for (int t = 0; t < HLT; t++) hv[cur ^ 1][t] = g_H2[nb + (size_t)t * trow];
            mub[cur ^ 1] = g_mean[(c + 1) * NC2 + n];
            vrb[cur ^ 1] = g_var [(c + 1) * NC2 + n];
        }
        const float mu  = mub[cur];
        const float inv = 1.0f / sqrtf(vrb[cur] + 1e-5f);
        float acc = 0.0f;
#pragma unroll
        for (int t = 0; t < HLT; t++) {
            const float h  = gn * (hv[cur][t] - mu) * inv + btn;
            v = v + (h - v) * 0.5f;
            acc += v;
        }
        out[(size_t)c * trow + idx] = acc * 0.125f;
    }
}

// ---------------------------------------------------------------------------
// Launch sequence (graph-capturable)
// ---------------------------------------------------------------------------
extern "C" void kernel_launch(void* const* d_in, const int* in_sizes, int n_in,
                              void* d_out, int out_size)
{
    (void)in_sizes; (void)n_in; (void)out_size;
    const float* x   = (const float*)d_in[0];
    const float* W0  = (const float*)d_in[1];
    const float* b0  = (const float*)d_in[2];
    const float* g0  = (const float*)d_in[3];
    const float* bt0 = (const float*)d_in[4];
    const float* W1  = (const float*)d_in[5];
    const float* b1  = (const float*)d_in[6];
    const float* g1  = (const float*)d_in[7];
    const float* bt1 = (const float*)d_in[8];
    const float* W2  = (const float*)d_in[9];
    const float* b2  = (const float*)d_in[10];
    const float* g2  = (const float*)d_in[11];
    const float* bt2 = (const float*)d_in[12];
    float* out = (float*)d_out;

    void *ph0, *ph1, *ph2, *ps0, *ps1;
    void *pw1h, *pw1m, *pw1l, *pw2h, *pw2m, *pw2l;
    cudaGetSymbolAddress(&ph0, g_H0);
    cudaGetSymbolAddress(&ph1, g_H1);
    cudaGetSymbolAddress(&ph2, g_H2);
    cudaGetSymbolAddress(&ps0, g_S0);
    cudaGetSymbolAddress(&ps1, g_S1);
    cudaGetSymbolAddress(&pw1h, g_W1h); cudaGetSymbolAddress(&pw1m, g_W1m); cudaGetSymbolAddress(&pw1l, g_W1l);
    cudaGetSymbolAddress(&pw2h, g_W2h); cudaGetSymbolAddress(&pw2m, g_W2m); cudaGetSymbolAddress(&pw2l, g_W2l);

    cudaFuncSetAttribute(gemm_spike<NC1, NC0>, cudaFuncAttributeMaxDynamicSharedMemorySize, SMEM_TC);
    cudaFuncSetAttribute(gemm_spike<NC2, NC1>, cudaFuncAttributeMaxDynamicSharedMemorySize, SMEM_TC);

    // weight splits for spike layers
    { int n = NC1 * NC0; split3<<<(n + 255) / 256, 256>>>(W1, (__nv_bfloat16*)pw1h, (__nv_bfloat16*)pw1m, (__nv_bfloat16*)pw1l, n); }
    { int n = NC2 * NC1; split3<<<(n + 255) / 256, 256>>>(W2, (__nv_bfloat16*)pw2h, (__nv_bfloat16*)pw2m, (__nv_bfloat16*)pw2l, n); }

    // Layer 0 (fp32, pipelined, proven arithmetic)
    gemm_f32<NC0, D_IN><<<dim3(NC0 / 128, ROWS / 128), 256>>>(x, W0, b0, (float*)ph0);
    bn_stats<0, NC0><<<dim3(NC0 / 256, CHUNKS), 256>>>();
    lif_hidden<0, NC0><<<(BATCH * NC0) / 256, 256>>>(g0, bt0);

    // Layer 1 (HMMA, exact bf16 spikes x 3-split W, R4-proven order)
    gemm_spike<NC1, NC0><<<dim3(NC1 / 128, ROWS / 128), 256, SMEM_TC>>>(
        (const __nv_bfloat16*)ps0, (const __nv_bfloat16*)pw1h, (const __nv_bfloat16*)pw1m,
        (const __nv_bfloat16*)pw1l, b1, (float*)ph1);
    bn_stats<1, NC1><<<dim3(NC1 / 256, CHUNKS), 256>>>();
    lif_hidden<1, NC1><<<(BATCH * NC1) / 256, 256>>>(g1, bt1);

    // Layer 2 (HMMA)
    gemm_spike<NC2, NC1><<<dim3(NC2 / 128, ROWS / 128), 256, SMEM_TC>>>(
        (const __nv_bfloat16*)ps1, (const __nv_bfloat16*)pw2h, (const __nv_bfloat16*)pw2m,
        (const __nv_bfloat16*)pw2l, b2, (float*)ph2);
    bn_stats<2, NC2><<<dim3(NC2 / 256, CHUNKS), 256>>>();
    lif_out<<<(BATCH * NC2) / 256, 256>>>(g2, bt2, out);
}

// round 17
// speedup vs baseline: 1.0525x; 1.0525x over previous
#include <cuda_runtime.h>
#include <cuda_bf16.h>
#include <cstdint>
#include <math.h>

#define T_TOTAL 1024
#define BATCH   32
#define D_IN    512
#define NC0     1024
#define NC1     1024
#define NC2     512
#define ROWS    (T_TOTAL * BATCH)   // 32768
#define CHUNKS  128
#define HLT     8

// ---------------------------------------------------------------------------
// Scratch (device globals; no cudaMalloc allowed)
// ---------------------------------------------------------------------------
__device__ float g_H0[(size_t)ROWS * NC0];
__device__ float g_H1[(size_t)ROWS * NC1];
__device__ float g_H2[(size_t)ROWS * NC2];
__device__ float g_mean[CHUNKS * NC0];
__device__ float g_var [CHUNKS * NC0];

__device__ __nv_bfloat16 g_S0[(size_t)ROWS * NC0];   // spikes (exact in bf16)
__device__ __nv_bfloat16 g_S1[(size_t)ROWS * NC1];
__device__ __nv_bfloat16 g_W1h[NC1 * NC0], g_W1m[NC1 * NC0], g_W1l[NC1 * NC0];
__device__ __nv_bfloat16 g_W2h[NC2 * NC1], g_W2m[NC2 * NC1], g_W2l[NC2 * NC1];

// ---------------------------------------------------------------------------
// PTX helpers (family-agnostic: mma.sync / ldmatrix / cp.async only)
// ---------------------------------------------------------------------------
__device__ __forceinline__ uint32_t smem_to_u32(const void* p) {
    uint32_t a;
    asm("{ .reg .u64 t; cvta.to.shared.u64 t, %1; cvt.u32.u64 %0, t; }" : "=r"(a) : "l"(p));
    return a;
}
__device__ __forceinline__ void ldsm_x4(uint32_t* r, uint32_t addr) {
    asm volatile("ldmatrix.sync.aligned.m8n8.x4.shared.b16 {%0,%1,%2,%3}, [%4];"
        : "=r"(r[0]), "=r"(r[1]), "=r"(r[2]), "=r"(r[3]) : "r"(addr));
}
__device__ __forceinline__ void mma16816(float* c, const uint32_t* a, const uint32_t* b) {
    asm volatile("mma.sync.aligned.m16n8k16.row.col.f32.bf16.bf16.f32 "
        "{%0,%1,%2,%3}, {%4,%5,%6,%7}, {%8,%9}, {%0,%1,%2,%3};"
        : "+f"(c[0]), "+f"(c[1]), "+f"(c[2]), "+f"(c[3])
        : "r"(a[0]), "r"(a[1]), "r"(a[2]), "r"(a[3]), "r"(b[0]), "r"(b[1]));
}
__device__ __forceinline__ void cpasync16(uint32_t dst, const void* src) {
    asm volatile("cp.async.cg.shared.global [%0], [%1], 16;" :: "r"(dst), "l"(src));
}

// SW64 swizzle (layout-only; bit-identical data)
#define SWZ64(off) ((off) ^ (((off) >> 3) & 0x30))
#define TB64   (128 * 64)          // one 128x32 bf16 tile = 8192 B
#define STG64  (4 * TB64)          // 1 A tile + 3 B tiles  = 32768 B
#define SMEM_TC (3 * STG64)        // 3 stages = 98304 B -> 2 CTAs/SM

// load one 128x32 bf16 tile: 512 granules of 16B, 2 per thread
__device__ __forceinline__ void load_tile(uint32_t dst, const __nv_bfloat16* __restrict__ src,
                                          int row0, int ldk, int k0, int tid)
{
    const char* gb = (const char*)(src + (size_t)row0 * ldk + k0);
    const size_t rs = (size_t)ldk * 2;
#pragma unroll
    for (int i = 0; i < 2; i++) {
        int idx = i * 256 + tid;
        int r = idx >> 2, g = idx & 3;
        uint32_t off = (uint32_t)(r * 64 + g * 16);
        cpasync16(dst + SWZ64(off), gb + (size_t)r * rs + g * 16);
    }
}

// ---------------------------------------------------------------------------
// HMMA GEMM for spike layers: C[M,N] = A * (Wh+Wm+Wl)^T + bias
// A = bf16 spikes (exact). 128x128 block tile, BK=32, 3-stage cp.async,
// 8 warps in 2(M)x4(N) (warp tile 64x32). SW64 swizzle; 2 CTAs/SM.
// Per-element accumulation sequence identical to the R4-proven order.
// ---------------------------------------------------------------------------
template <int N, int K>
__global__ void __launch_bounds__(256, 2) gemm_spike(
    const __nv_bfloat16* __restrict__ A,
    const __nv_bfloat16* __restrict__ Wh,
    const __nv_bfloat16* __restrict__ Wm,
    const __nv_bfloat16* __restrict__ Wl,
    const float* __restrict__ bias,
    float* __restrict__ C)
{
    constexpr int NCH = K / 32;
    const __nv_bfloat16* Bp[3] = {Wh, Wm, Wl};

    extern __shared__ __align__(128) char smem[];
    const uint32_t sb = smem_to_u32(smem);
    const int tid = threadIdx.x;
    const int l   = tid & 31;
    const int wid = tid >> 5;
    const int wm  = wid & 1;       // 2 warps along M (64 rows each)
    const int wn  = wid >> 1;      // 4 warps along N (32 cols each)
    const int n0  = blockIdx.x * 128;
    const int m0  = blockIdx.y * 128;

    float acc[4][4][4];
#pragma unroll
    for (int i = 0; i < 4; i++)
#pragma unroll
        for (int j = 0; j < 4; j++)
#pragma unroll
            for (int q = 0; q < 4; q++) acc[i][j][q] = 0.0f;

    const int rA = l & 15;
    const int cA = l >> 4;
    const int rB = ((l >> 4) & 1) * 8 + (l & 7);
    const int cB = (l >> 3) & 1;

#pragma unroll
    for (int pc = 0; pc < 2; pc++) {
        const uint32_t so = sb + (uint32_t)pc * STG64;
        load_tile(so, A, m0, K, pc * 32, tid);
#pragma unroll
        for (int b = 0; b < 3; b++) load_tile(so + (1 + b) * TB64, Bp[b], n0, K, pc * 32, tid);
        asm volatile("cp.async.commit_group;" ::: "memory");
    }

    for (int ch = 0; ch < NCH; ch++) {
        if (ch == NCH - 1) asm volatile("cp.async.wait_group 0;" ::: "memory");
        else               asm volatile("cp.async.wait_group 1;" ::: "memory");
        __syncthreads();

        if (ch + 2 < NCH) {
            const uint32_t so = sb + (uint32_t)((ch + 2) % 3) * STG64;
            const int k0 = (ch + 2) * 32;
            load_tile(so, A, m0, K, k0, tid);
#pragma unroll
            for (int b = 0; b < 3; b++) load_tile(so + (1 + b) * TB64, Bp[b], n0, K, k0, tid);
            asm volatile("cp.async.commit_group;" ::: "memory");
        }

        const uint32_t so = sb + (uint32_t)(ch % 3) * STG64;
#pragma unroll
        for (int ks = 0; ks < 2; ks++) {
            uint32_t af[4][4];
#pragma unroll
            for (int tm = 0; tm < 4; tm++) {
                uint32_t off = (uint32_t)((wm * 64 + tm * 16 + rA) * 64 + (ks * 2 + cA) * 16);
                ldsm_x4(af[tm], so + SWZ64(off));
            }
#pragma unroll
            for (int b = 0; b < 3; b++) {
                uint32_t bf[2][4];
#pragma unroll
                for (int g = 0; g < 2; g++) {
                    uint32_t off = (uint32_t)((wn * 32 + g * 16 + rB) * 64 + (ks * 2 + cB) * 16);
                    ldsm_x4(bf[g], so + (1 + b) * TB64 + SWZ64(off));
                }
#pragma unroll
                for (int tm = 0; tm < 4; tm++)
#pragma unroll
                    for (int n8 = 0; n8 < 4; n8++)
                        mma16816(acc[tm][n8], af[tm], &bf[n8 >> 1][(n8 & 1) * 2]);
            }
        }
    }

    // epilogue: acc + bias -> C (row-major fp32)
#pragma unroll
    for (int tm = 0; tm < 4; tm++) {
        const int mr = m0 + wm * 64 + tm * 16 + (l >> 2);
#pragma unroll
        for (int n8 = 0; n8 < 4; n8++) {
            const int col = n0 + wn * 32 + n8 * 8 + (l & 3) * 2;
            const float bx = bias[col], by = bias[col + 1];
            float2 v0, v1;
            v0.x = acc[tm][n8][0] + bx; v0.y = acc[tm][n8][1] + by;
            v1.x = acc[tm][n8][2] + bx; v1.y = acc[tm][n8][3] + by;
            *(float2*)(C + (size_t)mr * N + col)       = v0;
            *(float2*)(C + (size_t)(mr + 8) * N + col) = v1;
        }
    }
}

// ---------------------------------------------------------------------------
// fp32 GEMM for layer 0 — pipelined (double-buffered SMEM + register
// prefetch, one sync per k-chunk); R1-proven FMA order, bit-identical.
// ---------------------------------------------------------------------------
__device__ __forceinline__ int bswz(int col) {
    int g = col >> 2;
    int gs = g ^ (g >> 3);
    return (gs << 2) | (col & 3);
}

template <int N, int K>
__global__ __launch_bounds__(256, 2)
void gemm_f32(const float* __restrict__ A, const float* __restrict__ B,
              const float* __restrict__ bias, float* __restrict__ C)
{
    __shared__ float As[2][16][128];
    __shared__ float Bs[2][16][128];

    const int tid = threadIdx.x;
    const int m0  = blockIdx.y * 128;
    const int n0  = blockIdx.x * 128;
    const int tm  = (tid >> 4) << 3;
    const int tn  = (tid & 15) << 3;
    const int lr  = tid >> 2;
    const int lc  = (tid & 3) << 2;

    float acc[8][8];
#pragma unroll
    for (int i = 0; i < 8; i++)
#pragma unroll
        for (int j = 0; j < 8; j++) acc[i][j] = 0.0f;

    float4 av[2], bv[2];
#pragma unroll
    for (int h = 0; h < 2; h++) {
        const int r = lr + h * 64;
        av[h] = *(const float4*)(A + (size_t)(m0 + r) * K + lc);
        bv[h] = *(const float4*)(B + (size_t)(n0 + r) * K + lc);
    }

    for (int k0 = 0; k0 < K; k0 += 16) {
        const int buf = (k0 >> 4) & 1;
#pragma unroll
        for (int h = 0; h < 2; h++) {
            const int r = lr + h * 64;
            As[buf][lc + 0][r] = av[h].x; As[buf][lc + 1][r] = av[h].y;
            As[buf][lc + 2][r] = av[h].z; As[buf][lc + 3][r] = av[h].w;
            const int rsw = bswz(r);
            Bs[buf][lc + 0][rsw] = bv[h].x; Bs[buf][lc + 1][rsw] = bv[h].y;
            Bs[buf][lc + 2][rsw] = bv[h].z; Bs[buf][lc + 3][rsw] = bv[h].w;
        }
        if (k0 + 16 < K) {
#pragma unroll
            for (int h = 0; h < 2; h++) {
                const int r = lr + h * 64;
                av[h] = *(const float4*)(A + (size_t)(m0 + r) * K + (k0 + 16 + lc));
                bv[h] = *(const float4*)(B + (size_t)(n0 + r) * K + (k0 + 16 + lc));
            }
        }
        __syncthreads();
#pragma unroll
        for (int kk = 0; kk < 16; kk++) {
            float4 a0 = *(const float4*)&As[buf][kk][tm];
            float4 a1 = *(const float4*)&As[buf][kk][tm + 4];
            float4 b0 = *(const float4*)&Bs[buf][kk][bswz(tn)];
            float4 b1 = *(const float4*)&Bs[buf][kk][bswz(tn + 4)];
            float ar[8] = {a0.x, a0.y, a0.z, a0.w, a1.x, a1.y, a1.z, a1.w};
            float br[8] = {b0.x, b0.y, b0.z, b0.w, b1.x, b1.y, b1.z, b1.w};
#pragma unroll
            for (int i = 0; i < 8; i++)
#pragma unroll
                for (int j = 0; j < 8; j++)
                    acc[i][j] = fmaf(ar[i], br[j], acc[i][j]);
        }
    }

#pragma unroll
    for (int i = 0; i < 8; i++) {
        float4 o0, o1;
        o0.x = acc[i][0] + bias[n0 + tn + 0];
        o0.y = acc[i][1] + bias[n0 + tn + 1];
        o0.z = acc[i][2] + bias[n0 + tn + 2];
        o0.w = acc[i][3] + bias[n0 + tn + 3];
        o1.x = acc[i][4] + bias[n0 + tn + 4];
        o1.y = acc[i][5] + bias[n0 + tn + 5];
        o1.z = acc[i][6] + bias[n0 + tn + 6];
        o1.w = acc[i][7] + bias[n0 + tn + 7];
        float* cp = C + (size_t)(m0 + tm + i) * N + n0 + tn;
        *(float4*)cp       = o0;
        *(float4*)(cp + 4) = o1;
    }
}

// ---------------------------------------------------------------------------
// fp32 -> 3-way bf16 split (hi + mid + lo)
// ---------------------------------------------------------------------------
__global__ void __launch_bounds__(256) split3(const float* __restrict__ src,
                                              __nv_bfloat16* __restrict__ h,
                                              __nv_bfloat16* __restrict__ m,
                                              __nv_bfloat16* __restrict__ l, int n)
{
    int i = blockIdx.x * 256 + threadIdx.x;
    if (i >= n) return;
    float x  = src[i];
    __nv_bfloat16 hh = __float2bfloat16(x);
    float r1 = x - __bfloat162float(hh);
    __nv_bfloat16 mm = __float2bfloat16(r1);
    float r2 = r1 - __bfloat162float(mm);
    h[i] = hh; m[i] = mm; l[i] = __float2bfloat16(r2);
}

// ---------------------------------------------------------------------------
// BN stats (two-pass, scalar, 1 channel/thread — R4/R8-proven numerics)
// ---------------------------------------------------------------------------
template <int LAYER, int N>
__global__ __launch_bounds__(256)
void bn_stats()
{
    const float* __restrict__ H =
        (LAYER == 0) ? static_cast<const float*>(g_H0)
        : (LAYER == 1) ? static_cast<const float*>(g_H1)
                       : static_cast<const float*>(g_H2);
    const int ch = blockIdx.x * 256 + threadIdx.x;
    const int c  = blockIdx.y;
    const float* base = H + (size_t)c * 256 * N + ch;

    float s = 0.0f;
#pragma unroll 8
    for (int r = 0; r < 256; r++) s += base[(size_t)r * N];
    const float mu = s * 0.00390625f;

    float vs = 0.0f;
#pragma unroll 8
    for (int r = 0; r < 256; r++) {
        float d = base[(size_t)r * N] - mu;
        vs = fmaf(d, d, vs);
    }
    g_mean[c * N + ch] = mu;
    g_var [c * N + ch] = vs * 0.00390625f;
}

// ---------------------------------------------------------------------------
// Hidden LIF with chunk-ahead prefetch (identical FP sequence per neuron)
// ---------------------------------------------------------------------------
template <int LAYER, int N>
__global__ __launch_bounds__(256)
void lif_hidden(const float* __restrict__ g, const float* __restrict__ bt)
{
    const float* __restrict__ H =
        (LAYER == 0) ? static_cast<const float*>(g_H0)
                     : static_cast<const float*>(g_H1);
    __nv_bfloat16* __restrict__ S =
        (LAYER == 0) ? static_cast<__nv_bfloat16*>(g_S0)
                     : static_cast<__nv_bfloat16*>(g_S1);

    const int idx = blockIdx.x * 256 + threadIdx.x;
    const int n   = idx & (N - 1);
    const float gn  = g[n];
    const float btn = bt[n];
    const size_t trow = (size_t)BATCH * N;
    const __nv_bfloat16 one  = __float2bfloat16(1.0f);
    const __nv_bfloat16 zero = __float2bfloat16(0.0f);

    float hv[2][HLT];
    float mub[2], vrb[2];
#pragma unroll
    for (int t = 0; t < HLT; t++) hv[0][t] = H[(size_t)t * trow + idx];
    mub[0] = g_mean[n];
    vrb[0] = g_var[n];

    float v = 0.0f;
    for (int c = 0; c < CHUNKS; c++) {
        const int cur = c & 1;
        if (c + 1 < CHUNKS) {
            const size_t nb = (size_t)(c + 1) * HLT * trow + idx;
#pragma unroll
            for (int t = 0; t < HLT; t++) hv[cur ^ 1][t] = H[nb + (size_t)t * trow];
            mub[cur ^ 1] = g_mean[(c + 1) * N + n];
            vrb[cur ^ 1] = g_var [(c + 1) * N + n];
        }
        const float mu  = mub[cur];
        const float inv = 1.0f / sqrtf(vrb[cur] + 1e-5f);
        const size_t base = (size_t)c * HLT * trow + idx;
#pragma unroll
        for (int t = 0; t < HLT; t++) {
            const float hb = gn * (hv[cur][t] - mu) * inv + btn;
            v = v + (hb - v) * 0.5f;
            const bool sp = (v >= 1.0f);
            S[base + (size_t)t * trow] = sp ? one : zero;
            if (sp) v = 0.0f;
        }
    }
}

// ---------------------------------------------------------------------------
// Output layer: leaky integrator + chunk mean -> d_out [128, 32, 512]
// ---------------------------------------------------------------------------
__global__ __launch_bounds__(256)
void lif_out(const float* __restrict__ g, const float* __restrict__ bt,
             float* __restrict__ out)
{
    const int idx = blockIdx.x * 256 + threadIdx.x;
    const int n   = idx & (NC2 - 1);
    const float gn  = g[n];
    const float btn = bt[n];
    const size_t trow = (size_t)BATCH * NC2;

    float hv[2][HLT];
    float mub[2], vrb[2];
#pragma unroll
    for (int t = 0; t < HLT; t++) hv[0][t] = g_H2[(size_t)t * trow + idx];
    mub[0] = g_mean[n];
    vrb[0] = g_var[n];

    float v = 0.0f;
    for (int c = 0; c < CHUNKS; c++) {
        const int cur = c & 1;
        if (c + 1 < CHUNKS) {
            const size_t nb = (size_t)(c + 1) * HLT * trow + idx;
#pragma unroll
            for (int t = 0; t < HLT; t++) hv[cur ^ 1][t] = g_H2[nb + (size_t)t * trow];
            mub[cur ^ 1] = g_mean[(c + 1) * NC2 + n];
            vrb[cur ^ 1] = g_var [(c + 1) * NC2 + n];
        }
        const float mu  = mub[cur];
        const float inv = 1.0f / sqrtf(vrb[cur] + 1e-5f);
        float acc = 0.0f;
#pragma unroll
        for (int t = 0; t < HLT; t++) {
            const float h  = gn * (hv[cur][t] - mu) * inv + btn;
            v = v + (h - v) * 0.5f;
            acc += v;
        }
        out[(size_t)c * trow + idx] = acc * 0.125f;
    }
}

// ---------------------------------------------------------------------------
// Launch sequence (graph-capturable)
// ---------------------------------------------------------------------------
extern "C" void kernel_launch(void* const* d_in, const int* in_sizes, int n_in,
                              void* d_out, int out_size)
{
    (void)in_sizes; (void)n_in; (void)out_size;
    const float* x   = (const float*)d_in[0];
    const float* W0  = (const float*)d_in[1];
    const float* b0  = (const float*)d_in[2];
    const float* g0  = (const float*)d_in[3];
    const float* bt0 = (const float*)d_in[4];
    const float* W1  = (const float*)d_in[5];
    const float* b1  = (const float*)d_in[6];
    const float* g1  = (const float*)d_in[7];
    const float* bt1 = (const float*)d_in[8];
    const float* W2  = (const float*)d_in[9];
    const float* b2  = (const float*)d_in[10];
    const float* g2  = (const float*)d_in[11];
    const float* bt2 = (const float*)d_in[12];
    float* out = (float*)d_out;

    void *ph0, *ph1, *ph2, *ps0, *ps1;
    void *pw1h, *pw1m, *pw1l, *pw2h, *pw2m, *pw2l;
    cudaGetSymbolAddress(&ph0, g_H0);
    cudaGetSymbolAddress(&ph1, g_H1);
    cudaGetSymbolAddress(&ph2, g_H2);
    cudaGetSymbolAddress(&ps0, g_S0);
    cudaGetSymbolAddress(&ps1, g_S1);
    cudaGetSymbolAddress(&pw1h, g_W1h); cudaGetSymbolAddress(&pw1m, g_W1m); cudaGetSymbolAddress(&pw1l, g_W1l);
    cudaGetSymbolAddress(&pw2h, g_W2h); cudaGetSymbolAddress(&pw2m, g_W2m); cudaGetSymbolAddress(&pw2l, g_W2l);

    cudaFuncSetAttribute(gemm_spike<NC1, NC0>, cudaFuncAttributeMaxDynamicSharedMemorySize, SMEM_TC);
    cudaFuncSetAttribute(gemm_spike<NC2, NC1>, cudaFuncAttributeMaxDynamicSharedMemorySize, SMEM_TC);

    // weight splits for spike layers
    { int n = NC1 * NC0; split3<<<(n + 255) / 256, 256>>>(W1, (__nv_bfloat16*)pw1h, (__nv_bfloat16*)pw1m, (__nv_bfloat16*)pw1l, n); }
    { int n = NC2 * NC1; split3<<<(n + 255) / 256, 256>>>(W2, (__nv_bfloat16*)pw2h, (__nv_bfloat16*)pw2m, (__nv_bfloat16*)pw2l, n); }

    // Layer 0 (fp32, pipelined, proven arithmetic)
    gemm_f32<NC0, D_IN><<<dim3(NC0 / 128, ROWS / 128), 256>>>(x, W0, b0, (float*)ph0);
    bn_stats<0, NC0><<<dim3(NC0 / 256, CHUNKS), 256>>>();
    lif_hidden<0, NC0><<<(BATCH * NC0) / 256, 256>>>(g0, bt0);

    // Layer 1 (HMMA, exact bf16 spikes x 3-split W, R4-proven order)
    gemm_spike<NC1, NC0><<<dim3(NC1 / 128, ROWS / 128), 256, SMEM_TC>>>(
        (const __nv_bfloat16*)ps0, (const __nv_bfloat16*)pw1h, (const __nv_bfloat16*)pw1m,
        (const __nv_bfloat16*)pw1l, b1, (float*)ph1);
    bn_stats<1, NC1><<<dim3(NC1 / 256, CHUNKS), 256>>>();
    lif_hidden<1, NC1><<<(BATCH * NC1) / 256, 256>>>(g1, bt1);

    // Layer 2 (HMMA)
    gemm_spike<NC2, NC1><<<dim3(NC2 / 128, ROWS / 128), 256, SMEM_TC>>>(
        (const __nv_bfloat16*)ps1, (const __nv_bfloat16*)pw2h, (const __nv_bfloat16*)pw2m,
        (const __nv_bfloat16*)pw2l, b2, (float*)ph2);
    bn_stats<2, NC2><<<dim3(NC2 / 256, CHUNKS), 256>>>();
    lif_out<<<(BATCH * NC2) / 256, 256>>>(g2, bt2, out);
}